// round 14
// baseline (speedup 1.0000x reference)
#include <cuda_runtime.h>
#include <cuda_fp16.h>
#include <math.h>
#include <stdint.h>

// Problem shape (fixed)
static constexpr int Bb = 4;
static constexpr int Tt = 2048;
static constexpr int Dd = 1024;
static constexpr int Hh = 16;
static constexpr int HDd = 64;
static constexpr int DFf = 4096;
static constexpr int Mrows = Bb * Tt;   // 8192
static constexpr int D3 = 3 * Dd;       // 3072

// ---------------- scratch (device globals; no allocation allowed) ----------
__device__ float g_h[(size_t)Mrows * Dd];
// fp16 activations / weights
__device__ __half g_xh[(size_t)Mrows * Dd];
__device__ __half g_qkvh[(size_t)Mrows * D3];
__device__ __half g_attnh[(size_t)Mrows * Dd];
__device__ __half g_projh[(size_t)Mrows * Dd];
__device__ __half g_hh[(size_t)Mrows * Dd];
__device__ __half g_ff1h[(size_t)Mrows * DFf];
__device__ __half g_ff2h[(size_t)Mrows * Dd];
__device__ __half g_wqkvh[(size_t)Dd * D3];
__device__ __half g_woh[(size_t)Dd * Dd];
__device__ __half g_w1h[(size_t)Dd * DFf];
__device__ __half g_w2h[(size_t)DFf * Dd];

// ---------------- helpers ----------------
__device__ __forceinline__ float gelu_exact(float x) {
    return 0.5f * x * (1.0f + erff(x * 0.70710678118654752f));
}

__device__ __forceinline__ void cp_async16(uint32_t smem_addr, const void* gptr) {
    asm volatile("cp.async.cg.shared.global [%0], [%1], 16;\n"
                 :: "r"(smem_addr), "l"(gptr));
}
__device__ __forceinline__ void cp_commit() {
    asm volatile("cp.async.commit_group;\n");
}
template <int N>
__device__ __forceinline__ void cp_wait() {
    asm volatile("cp.async.wait_group %0;\n" :: "n"(N));
}

__device__ __forceinline__ uint32_t smem_u32(const void* p) {
    return (uint32_t)__cvta_generic_to_shared(p);
}

__device__ __forceinline__ void mma_f16(
    float& c0, float& c1, float& c2, float& c3,
    uint32_t a0, uint32_t a1, uint32_t a2, uint32_t a3,
    uint32_t b0, uint32_t b1)
{
    asm volatile(
        "mma.sync.aligned.m16n8k16.row.col.f32.f16.f16.f32 "
        "{%0,%1,%2,%3}, {%4,%5,%6,%7}, {%8,%9}, {%0,%1,%2,%3};\n"
        : "+f"(c0), "+f"(c1), "+f"(c2), "+f"(c3)
        : "r"(a0), "r"(a1), "r"(a2), "r"(a3), "r"(b0), "r"(b1));
}

__device__ __forceinline__ void ldsm_x4(
    uint32_t& r0, uint32_t& r1, uint32_t& r2, uint32_t& r3, uint32_t addr)
{
    asm volatile("ldmatrix.sync.aligned.m8n8.x4.shared.b16 {%0,%1,%2,%3}, [%4];"
                 : "=r"(r0), "=r"(r1), "=r"(r2), "=r"(r3) : "r"(addr));
}
__device__ __forceinline__ void ldsm_x4_t(
    uint32_t& r0, uint32_t& r1, uint32_t& r2, uint32_t& r3, uint32_t addr)
{
    asm volatile("ldmatrix.sync.aligned.m8n8.x4.trans.shared.b16 {%0,%1,%2,%3}, [%4];"
                 : "=r"(r0), "=r"(r1), "=r"(r2), "=r"(r3) : "r"(addr));
}

__device__ __forceinline__ uint32_t pack_h2(float a, float b) {
    __half2 h = __floats2half2_rn(a, b);
    return *(uint32_t*)&h;
}

// ---------------- fp16 tensor-core GEMM, cp.async 3-stage, BK=64 ------------
// C[M,N] = A[M,K] @ B[K,N] (+bias)(+gelu).
// Block 128x128, BK=64, 128 threads (4 warps), warp tile 64x64.
// A smem: [128 rows][72 halfs] (144 B rows: stride ≡ 4 mod 32 banks ->
//   conflict-free ldmatrix without XOR).  B smem: [64 rows][128 halfs]
//   (256 B rows, 16B-chunk XOR swizzle chunk ^= (row & 7)).
static constexpr int HAS_B = 144;                    // A row bytes
static constexpr int HA_BYTES = 128 * HAS_B;         // 18432
static constexpr int HB_BYTES = 64 * 256;            // 16384
static constexpr int HSTAGE = HA_BYTES + HB_BYTES;   // 34816
static constexpr int HSTAGES = 3;
static constexpr int HGEMM_SMEM = HSTAGES * HSTAGE;  // 104448 B

// OUTH: 0 = float out, 1 = half out.  EPI: 0 none, 1 +bias, 2 +bias+gelu
template <int OUTH, int EPI>
__global__ __launch_bounds__(128) void gemm_h_kernel(
    const __half* __restrict__ A, const __half* __restrict__ Bm,
    const float* __restrict__ bias, void* __restrict__ Cout,
    int M, int N, int K)
{
    extern __shared__ __align__(128) char smem[];
    const uint32_t sbase = smem_u32(smem);

    const int tid = threadIdx.x;
    const int warp = tid >> 5;
    const int lane = tid & 31;
    const int lq = lane >> 2;
    const int lr = lane & 3;

    const int bm = blockIdx.y * 128;
    const int bn = blockIdx.x * 128;
    const int wm = (warp & 1) * 64;
    const int wn = (warp >> 1) * 64;

    // A: 128 rows x 8 chunks = 1024 chunks; 8 per thread
    // B: 64 rows x 16 chunks = 1024 chunks; 8 per thread
    const int a_c = tid & 7;                 // A chunk within row
    const int b_c = tid & 15;                // B chunk within row
    int a_r[8], b_k[8];
    uint32_t sa[8], sb[8];
#pragma unroll
    for (int i = 0; i < 8; i++) {
        const int ida = tid + i * 128;
        a_r[i] = ida >> 3;
        sa[i] = a_r[i] * HAS_B + a_c * 16;              // no XOR (padded)
        const int idb = tid + i * 128;
        b_k[i] = idb >> 4;
        sb[i] = HA_BYTES + b_k[i] * 256 + ((b_c ^ (b_k[i] & 7)) * 16);
    }

    const __half* Ag = A + (size_t)bm * K;
    const __half* Bg = Bm + bn;

    auto issue = [&](int kt, int stage) {
        const uint32_t st = sbase + stage * HSTAGE;
        const int k0 = kt * 64;
#pragma unroll
        for (int i = 0; i < 8; i++) {
            cp_async16(st + sa[i], Ag + (size_t)a_r[i] * K + k0 + a_c * 8);
            cp_async16(st + sb[i], Bg + (size_t)(k0 + b_k[i]) * N + b_c * 8);
        }
        cp_commit();
    };

    const int KT = K / 64;
    issue(0, 0);
    issue(1, 1);

    float acc[4][8][4];
#pragma unroll
    for (int i = 0; i < 4; i++)
#pragma unroll
        for (int j = 0; j < 8; j++)
#pragma unroll
            for (int r = 0; r < 4; r++) acc[i][j][r] = 0.0f;

    const int a_lrow = lane & 15;
    const int a_lkof = (lane >> 4) * 16;
    const int b_lrow = lane & 15;
    const int b_lnof = (lane >> 4) * 8;

    int stage = 0;
    for (int it = 0; it < KT; ++it) {
        cp_wait<1>();
        __syncthreads();
        // Safe to refill stage (it+2)%3 ≡ (it-1)%3: its readers finished
        // before this barrier (they passed the barrier of iteration it).
        if (it + 2 < KT) {
            int ns = stage + 2; if (ns >= 3) ns -= 3;
            issue(it + 2, ns);
        }

        const uint32_t Asb = sbase + stage * HSTAGE;
        const uint32_t Bsb = Asb + HA_BYTES;

#pragma unroll
        for (int kk = 0; kk < 64; kk += 16) {
            uint32_t af[4][4];
#pragma unroll
            for (int mt = 0; mt < 4; mt++) {
                const int row = wm + mt * 16 + a_lrow;
                ldsm_x4(af[mt][0], af[mt][1], af[mt][2], af[mt][3],
                        Asb + row * HAS_B + kk * 2 + a_lkof);
            }
            uint32_t bf[8][2];
#pragma unroll
            for (int pr = 0; pr < 4; pr++) {
                const int r = kk + b_lrow;
                const int n0 = wn + pr * 16 + b_lnof;
                const uint32_t addr =
                    Bsb + r * 256 + (((n0 >> 3) ^ (r & 7)) * 16);
                ldsm_x4_t(bf[pr * 2][0], bf[pr * 2][1],
                          bf[pr * 2 + 1][0], bf[pr * 2 + 1][1], addr);
            }
#pragma unroll
            for (int mt = 0; mt < 4; mt++)
#pragma unroll
                for (int nt = 0; nt < 8; nt++)
                    mma_f16(acc[mt][nt][0], acc[mt][nt][1],
                            acc[mt][nt][2], acc[mt][nt][3],
                            af[mt][0], af[mt][1], af[mt][2], af[mt][3],
                            bf[nt][0], bf[nt][1]);
        }
        if (++stage >= 3) stage -= 3;
    }

#pragma unroll
    for (int mt = 0; mt < 4; mt++) {
#pragma unroll
        for (int nt = 0; nt < 8; nt++) {
            const int col = bn + wn + nt * 8 + 2 * lr;
#pragma unroll
            for (int half_i = 0; half_i < 2; half_i++) {
                const int row = bm + wm + mt * 16 + lq + half_i * 8;
                float v0 = acc[mt][nt][half_i * 2 + 0];
                float v1 = acc[mt][nt][half_i * 2 + 1];
                if (EPI >= 1) {
                    v0 += bias[col];
                    v1 += bias[col + 1];
                }
                if (EPI == 2) {
                    v0 = gelu_exact(v0);
                    v1 = gelu_exact(v1);
                }
                if (OUTH) {
                    __half2 hv = __floats2half2_rn(v0, v1);
                    *(__half2*)((__half*)Cout + (size_t)row * N + col) = hv;
                } else {
                    *(float2*)((float*)Cout + (size_t)row * N + col) =
                        make_float2(v0, v1);
                }
            }
        }
    }
}

// ---------------- fp32 -> fp16 converts -------------------------------------
__global__ __launch_bounds__(256) void cvt_h_kernel(
    const float* __restrict__ in, __half* __restrict__ out)
{
    const size_t i = ((size_t)blockIdx.x * 256 + threadIdx.x) * 4;
    float4 v = *(const float4*)&in[i];
    *(__half2*)&out[i]     = __floats2half2_rn(v.x, v.y);
    *(__half2*)&out[i + 2] = __floats2half2_rn(v.z, v.w);
}

__global__ __launch_bounds__(256) void cvt_h_strided_kernel(
    const float* __restrict__ in, __half* __restrict__ out,
    int C, int ldo, int coff)
{
    const size_t i = ((size_t)blockIdx.x * 256 + threadIdx.x) * 4;
    const int r = (int)(i / C);
    const int c = (int)(i % C);
    float4 v = *(const float4*)&in[i];
    __half* o = out + (size_t)r * ldo + coff + c;
    *(__half2*)&o[0] = __floats2half2_rn(v.x, v.y);
    *(__half2*)&o[2] = __floats2half2_rn(v.z, v.w);
}

// ---------------- fp16 flash attention --------------------------------------
static constexpr int FQ_OFF = 0;
static constexpr int FK_OFF = 16384;
static constexpr int FV_OFF = 32768;
static constexpr int FH_SMEM = 49152;

__global__ __launch_bounds__(256) void flash_h_kernel(
    const __half* __restrict__ QKV, int ldqkv, __half* __restrict__ Ob)
{
    extern __shared__ __align__(128) char fsm[];
    const uint32_t sbase = smem_u32(fsm);

    const int tid = threadIdx.x;
    const int warp = tid >> 5;
    const int lane = tid & 31;
    const int lq = lane >> 2;
    const int lr = lane & 3;

    const int b = blockIdx.y / Hh;
    const int h = blockIdx.y % Hh;
    const int q0 = blockIdx.x * 128;
    const int w16 = warp * 16;

    const __half* Qb = QKV + h * HDd;
    const __half* Kb = QKV + Dd + h * HDd;
    const __half* Vb = QKV + 2 * Dd + h * HDd;

    int kv_r[2], kv_c[2];
#pragma unroll
    for (int it = 0; it < 2; it++) {
        const int id = tid + it * 256;
        kv_r[it] = id >> 3;
        kv_c[it] = id & 7;
    }

    auto issue_kv = [&](int tile, int buf) {
        const size_t baseKV = ((size_t)(b * Tt + tile * 64)) * ldqkv;
        const uint32_t kst = sbase + FK_OFF + buf * 8192;
        const uint32_t vst = sbase + FV_OFF + buf * 8192;
#pragma unroll
        for (int it = 0; it < 2; it++) {
            const int r = kv_r[it], c = kv_c[it];
            const size_t g = baseKV + (size_t)r * ldqkv + c * 8;
            const uint32_t so = r * 128 + ((c ^ (r & 7)) * 16);
            cp_async16(kst + so, Kb + g);
            cp_async16(vst + so, Vb + g);
        }
        cp_commit();
    };

    issue_kv(0, 0);

    {
        const size_t baseQ = ((size_t)(b * Tt + q0)) * ldqkv;
#pragma unroll
        for (int it = 0; it < 4; it++) {
            const int id = tid + it * 256;
            const int r = id >> 3, c = id & 7;
            uint4 v = *(const uint4*)&Qb[baseQ + (size_t)r * ldqkv + c * 8];
            *(uint4*)(fsm + FQ_OFF + r * 128 + ((c ^ (r & 7)) * 16)) = v;
        }
    }
    __syncthreads();

    uint32_t qa[4][4];
    {
        const int arow = w16 + (lane & 15);
        const __half2 sc2 = __float2half2_rn(0.125f);
#pragma unroll
        for (int kc = 0; kc < 4; kc++) {
            const int chunk = kc * 2 + (lane >> 4);
            const uint32_t addr =
                sbase + FQ_OFF + arow * 128 + ((chunk ^ (arow & 7)) * 16);
            ldsm_x4(qa[kc][0], qa[kc][1], qa[kc][2], qa[kc][3], addr);
#pragma unroll
            for (int r = 0; r < 4; r++) {
                __half2 t = *(__half2*)&qa[kc][r];
                t = __hmul2(t, sc2);
                qa[kc][r] = *(uint32_t*)&t;
            }
        }
    }

    float o[8][4];
#pragma unroll
    for (int nt = 0; nt < 8; nt++)
#pragma unroll
        for (int r = 0; r < 4; r++) o[nt][r] = 0.0f;
    float m0 = -INFINITY, m1 = -INFINITY;
    float l0 = 0.0f, l1 = 0.0f;

    const int kv_group = lane >> 3;
    const int kv_within = lane & 7;

    const int NT = Tt / 64;
    for (int t = 0; t < NT; ++t) {
        if (t + 1 < NT) issue_kv(t + 1, (t + 1) & 1);
        cp_wait<1>();
        __syncthreads();

        const uint32_t kbase = sbase + FK_OFF + (t & 1) * 8192;
        const uint32_t vbase = sbase + FV_OFF + (t & 1) * 8192;

        float s[8][4];
#pragma unroll
        for (int nt = 0; nt < 8; nt++)
#pragma unroll
            for (int r = 0; r < 4; r++) s[nt][r] = 0.0f;

#pragma unroll
        for (int kc = 0; kc < 4; kc++) {
#pragma unroll
            for (int ntp = 0; ntp < 4; ntp++) {
                const int row = ntp * 16 + (kv_group >> 1) * 8 + kv_within;
                const int chunk = kc * 2 + (kv_group & 1);
                uint32_t b0a, b1a, b0b, b1b;
                ldsm_x4(b0a, b1a, b0b, b1b,
                        kbase + row * 128 + ((chunk ^ (row & 7)) * 16));
                mma_f16(s[ntp * 2][0], s[ntp * 2][1], s[ntp * 2][2], s[ntp * 2][3],
                        qa[kc][0], qa[kc][1], qa[kc][2], qa[kc][3], b0a, b1a);
                mma_f16(s[ntp * 2 + 1][0], s[ntp * 2 + 1][1],
                        s[ntp * 2 + 1][2], s[ntp * 2 + 1][3],
                        qa[kc][0], qa[kc][1], qa[kc][2], qa[kc][3], b0b, b1b);
            }
        }

        float rm0 = -INFINITY, rm1 = -INFINITY;
#pragma unroll
        for (int nt = 0; nt < 8; nt++) {
            rm0 = fmaxf(rm0, fmaxf(s[nt][0], s[nt][1]));
            rm1 = fmaxf(rm1, fmaxf(s[nt][2], s[nt][3]));
        }
        rm0 = fmaxf(rm0, __shfl_xor_sync(0xffffffffu, rm0, 1));
        rm0 = fmaxf(rm0, __shfl_xor_sync(0xffffffffu, rm0, 2));
        rm1 = fmaxf(rm1, __shfl_xor_sync(0xffffffffu, rm1, 1));
        rm1 = fmaxf(rm1, __shfl_xor_sync(0xffffffffu, rm1, 2));
        const float mn0 = fmaxf(m0, rm0);
        const float mn1 = fmaxf(m1, rm1);
        const float alpha0 = __expf(m0 - mn0);
        const float alpha1 = __expf(m1 - mn1);

        float p[8][4];
        float rs0 = 0.0f, rs1 = 0.0f;
#pragma unroll
        for (int nt = 0; nt < 8; nt++) {
            p[nt][0] = __expf(s[nt][0] - mn0);
            p[nt][1] = __expf(s[nt][1] - mn0);
            p[nt][2] = __expf(s[nt][2] - mn1);
            p[nt][3] = __expf(s[nt][3] - mn1);
            rs0 += p[nt][0] + p[nt][1];
            rs1 += p[nt][2] + p[nt][3];
        }
        rs0 += __shfl_xor_sync(0xffffffffu, rs0, 1);
        rs0 += __shfl_xor_sync(0xffffffffu, rs0, 2);
        rs1 += __shfl_xor_sync(0xffffffffu, rs1, 1);
        rs1 += __shfl_xor_sync(0xffffffffu, rs1, 2);

        l0 = l0 * alpha0 + rs0;
        l1 = l1 * alpha1 + rs1;
        m0 = mn0;
        m1 = mn1;
#pragma unroll
        for (int nt = 0; nt < 8; nt++) {
            o[nt][0] *= alpha0; o[nt][1] *= alpha0;
            o[nt][2] *= alpha1; o[nt][3] *= alpha1;
        }

        uint32_t pa[4][4];
#pragma unroll
        for (int kc = 0; kc < 4; kc++) {
            pa[kc][0] = pack_h2(p[2 * kc][0], p[2 * kc][1]);
            pa[kc][1] = pack_h2(p[2 * kc][2], p[2 * kc][3]);
            pa[kc][2] = pack_h2(p[2 * kc + 1][0], p[2 * kc + 1][1]);
            pa[kc][3] = pack_h2(p[2 * kc + 1][2], p[2 * kc + 1][3]);
        }

#pragma unroll
        for (int kc = 0; kc < 4; kc++) {
#pragma unroll
            for (int ntp = 0; ntp < 4; ntp++) {
                const int row = kc * 16 + (kv_group & 1) * 8 + kv_within;
                const int chunk = ntp * 2 + (kv_group >> 1);
                uint32_t v0, v1, v2, v3;
                ldsm_x4_t(v0, v1, v2, v3,
                          vbase + row * 128 + ((chunk ^ (row & 7)) * 16));
                mma_f16(o[ntp * 2][0], o[ntp * 2][1], o[ntp * 2][2], o[ntp * 2][3],
                        pa[kc][0], pa[kc][1], pa[kc][2], pa[kc][3], v0, v1);
                mma_f16(o[ntp * 2 + 1][0], o[ntp * 2 + 1][1],
                        o[ntp * 2 + 1][2], o[ntp * 2 + 1][3],
                        pa[kc][0], pa[kc][1], pa[kc][2], pa[kc][3], v2, v3);
            }
        }
        __syncthreads();
    }

    const float inv0 = 1.0f / l0;
    const float inv1 = 1.0f / l1;
    const int r0 = q0 + w16 + lq;
    const int r1 = r0 + 8;
    const size_t base0 = ((size_t)(b * Tt + r0)) * Dd + h * HDd;
    const size_t base1 = ((size_t)(b * Tt + r1)) * Dd + h * HDd;
#pragma unroll
    for (int nt = 0; nt < 8; nt++) {
        const int c = nt * 8 + 2 * lr;
        *(__half2*)&Ob[base0 + c] =
            __floats2half2_rn(o[nt][0] * inv0, o[nt][1] * inv0);
        *(__half2*)&Ob[base1 + c] =
            __floats2half2_rn(o[nt][2] * inv1, o[nt][3] * inv1);
    }
}

// ---------------- residual add + LayerNorm (fp32 A + fp16 B) ----------------
__device__ __forceinline__ float block_sum_1024(float v, float* red) {
    const int tid = threadIdx.x;
    __syncthreads();
#pragma unroll
    for (int o = 16; o > 0; o >>= 1)
        v += __shfl_xor_sync(0xffffffffu, v, o);
    if ((tid & 31) == 0) red[tid >> 5] = v;
    __syncthreads();
    float t = (tid < 8) ? red[tid] : 0.0f;
    if (tid < 32) {
#pragma unroll
        for (int o = 4; o > 0; o >>= 1)
            t += __shfl_xor_sync(0xffffffffu, t, o);
        if (tid == 0) red[0] = t;
    }
    __syncthreads();
    return red[0];
}

__global__ __launch_bounds__(256) void add_ln_kernel(
    const float* __restrict__ A, const __half* __restrict__ Bv,
    const float* __restrict__ g, const float* __restrict__ be,
    float* __restrict__ out, __half* __restrict__ outh)
{
    __shared__ float red[8];
    const int row = blockIdx.x;
    const int tid = threadIdx.x;
    const size_t base = (size_t)row * Dd;
    const int c = tid * 4;

    float4 a = *(const float4*)&A[base + c];
    __half2 bh0 = *(const __half2*)&Bv[base + c];
    __half2 bh1 = *(const __half2*)&Bv[base + c + 2];
    float2 fb0 = __half22float2(bh0);
    float2 fb1 = __half22float2(bh1);
    float v0 = a.x + fb0.x, v1 = a.y + fb0.y, v2 = a.z + fb1.x, v3 = a.w + fb1.y;

    float s = block_sum_1024(v0 + v1 + v2 + v3, red);
    const float mu = s * (1.0f / Dd);
    float d0 = v0 - mu, d1 = v1 - mu, d2 = v2 - mu, d3 = v3 - mu;
    float q = block_sum_1024(d0 * d0 + d1 * d1 + d2 * d2 + d3 * d3, red);
    const float inv = rsqrtf(q * (1.0f / Dd) + 1e-5f);

    float4 gv = *(const float4*)&g[c];
    float4 bev = *(const float4*)&be[c];
    float4 o;
    o.x = d0 * inv * gv.x + bev.x;
    o.y = d1 * inv * gv.y + bev.y;
    o.z = d2 * inv * gv.z + bev.z;
    o.w = d3 * inv * gv.w + bev.w;
    *(float4*)&out[base + c] = o;
    if (outh != nullptr) {
        *(__half2*)&outh[base + c]     = __floats2half2_rn(o.x, o.y);
        *(__half2*)&outh[base + c + 2] = __floats2half2_rn(o.z, o.w);
    }
}

// ---------------- orchestration --------------------------------------------
extern "C" void kernel_launch(void* const* d_in, const int* in_sizes, int n_in,
                              void* d_out, int out_size)
{
    const float* x   = (const float*)d_in[0];
    const float* wq  = (const float*)d_in[1];
    const float* wk  = (const float*)d_in[2];
    const float* wv  = (const float*)d_in[3];
    const float* wo  = (const float*)d_in[4];
    const float* w1  = (const float*)d_in[5];
    const float* b1  = (const float*)d_in[6];
    const float* w2  = (const float*)d_in[7];
    const float* b2  = (const float*)d_in[8];
    const float* g1  = (const float*)d_in[9];
    const float* be1 = (const float*)d_in[10];
    const float* g2  = (const float*)d_in[11];
    const float* be2 = (const float*)d_in[12];

    float *h;
    __half *xh, *qkvh, *attnh, *projh, *hh, *ff1h, *ff2h;
    __half *wqkvh, *woh, *w1h, *w2h;
    cudaGetSymbolAddress((void**)&h,     g_h);
    cudaGetSymbolAddress((void**)&xh,    g_xh);
    cudaGetSymbolAddress((void**)&qkvh,  g_qkvh);
    cudaGetSymbolAddress((void**)&attnh, g_attnh);
    cudaGetSymbolAddress((void**)&projh, g_projh);
    cudaGetSymbolAddress((void**)&hh,    g_hh);
    cudaGetSymbolAddress((void**)&ff1h,  g_ff1h);
    cudaGetSymbolAddress((void**)&ff2h,  g_ff2h);
    cudaGetSymbolAddress((void**)&wqkvh, g_wqkvh);
    cudaGetSymbolAddress((void**)&woh,   g_woh);
    cudaGetSymbolAddress((void**)&w1h,   g_w1h);
    cudaGetSymbolAddress((void**)&w2h,   g_w2h);

    cudaFuncSetAttribute(gemm_h_kernel<1, 0>,
                         cudaFuncAttributeMaxDynamicSharedMemorySize, HGEMM_SMEM);
    cudaFuncSetAttribute(gemm_h_kernel<1, 1>,
                         cudaFuncAttributeMaxDynamicSharedMemorySize, HGEMM_SMEM);
    cudaFuncSetAttribute(gemm_h_kernel<1, 2>,
                         cudaFuncAttributeMaxDynamicSharedMemorySize, HGEMM_SMEM);
    cudaFuncSetAttribute(flash_h_kernel,
                         cudaFuncAttributeMaxDynamicSharedMemorySize, FH_SMEM);

    auto cvt = [](const float* in, __half* out, size_t n) {
        cvt_h_kernel<<<(unsigned)(n / 1024), 256>>>(in, out);
    };
    cvt(x,  xh,  (size_t)Mrows * Dd);
    cvt_h_strided_kernel<<<(unsigned)((size_t)Dd * Dd / 1024), 256>>>(
        wq, wqkvh, Dd, D3, 0);
    cvt_h_strided_kernel<<<(unsigned)((size_t)Dd * Dd / 1024), 256>>>(
        wk, wqkvh, Dd, D3, Dd);
    cvt_h_strided_kernel<<<(unsigned)((size_t)Dd * Dd / 1024), 256>>>(
        wv, wqkvh, Dd, D3, 2 * Dd);
    cvt(wo, woh, (size_t)Dd * Dd);
    cvt(w1, w1h, (size_t)Dd * DFf);
    cvt(w2, w2h, (size_t)DFf * Dd);

    const dim3 gblk(128);
    const dim3 gQKV(D3  / 128, Mrows / 128);  // (24, 64)
    const dim3 gD  (Dd  / 128, Mrows / 128);  // (8, 64)
    const dim3 gDF (DFf / 128, Mrows / 128);  // (32, 64)

    gemm_h_kernel<1, 0><<<gQKV, gblk, HGEMM_SMEM>>>(xh, wqkvh, nullptr, qkvh,
                                                    Mrows, D3, Dd);

    flash_h_kernel<<<dim3(Tt / 128, Bb * Hh), dim3(256), FH_SMEM>>>(qkvh, D3, attnh);

    gemm_h_kernel<1, 0><<<gD, gblk, HGEMM_SMEM>>>(attnh, woh, nullptr, projh,
                                                  Mrows, Dd, Dd);

    add_ln_kernel<<<Mrows, 256>>>(x, projh, g1, be1, h, hh);

    gemm_h_kernel<1, 2><<<gDF, gblk, HGEMM_SMEM>>>(hh, w1h, b1, ff1h, Mrows, DFf, Dd);
    gemm_h_kernel<1, 1><<<gD,  gblk, HGEMM_SMEM>>>(ff1h, w2h, b2, ff2h, Mrows, Dd, DFf);

    add_ln_kernel<<<Mrows, 256>>>(h, ff2h, g2, be2, (float*)d_out, nullptr);
}